// round 2
// baseline (speedup 1.0000x reference)
#include <cuda_runtime.h>
#include <math.h>

#define BB   8
#define TT   2048
#define EE   512
#define HH   8
#define HD   64
#define NQH  4
#define NLAY 2
#define NQF  8
#define FFND 2048
#define BTN  (BB*TT)

// ---- scratch (static device globals; no allocation allowed) ----
static __device__ float d_q [(size_t)BTN*EE];
static __device__ float d_k [(size_t)BTN*EE];
static __device__ float d_v [(size_t)BTN*EE];
static __device__ float d_s [(size_t)BB*TT*TT];
static __device__ float d_o [(size_t)BTN*EE];
static __device__ float d_x1[(size_t)BTN*EE];
static __device__ float d_h1[(size_t)BTN*FFND];
static __device__ float d_f [(size_t)BTN*EE];
// closed-form circuit constants:  qout = A*cos(u) + B*sin(u)
static __device__ float g_attA[HH*NQH];
static __device__ float g_attB[HH*NQH];
static __device__ float g_ffnA[NQF];
static __device__ float g_ffnB[NQF];

// ============================================================================
// Tiny kernel: simulate the parameter-only part of each circuit once,
// store <Z_q> and -<X_q> of the fixed state.
// Wire q lives at bit (n-1-q) of the flat amplitude index (matches reference).
// ============================================================================
__global__ void k_circuits(const float* __restrict__ hp, const float* __restrict__ fp)
{
    __shared__ float fpsi[256];
    const int t = threadIdx.x;
    if (t < HH) {
        float psi[16];
        #pragma unroll
        for (int i = 0; i < 16; i++) psi[i] = 0.f;
        psi[0] = 1.f;
        for (int l = 0; l < NLAY; l++) {
            for (int q = 0; q < NQH; q++) {
                float th = 0.5f * hp[t*NLAY*NQH + l*NQH + q];
                float c = cosf(th), s = sinf(th);
                int m = 1 << (NQH-1-q);
                for (int i = 0; i < 16; i++) {
                    if (!(i & m)) {
                        float a0 = psi[i], a1 = psi[i|m];
                        psi[i]   = c*a0 - s*a1;
                        psi[i|m] = s*a0 + c*a1;
                    }
                }
            }
            for (int q = 0; q < NQH; q++) {               // CNOT chain + ring
                int cm = 1 << (NQH-1-q), tm = 1 << (NQH-1-((q+1)%NQH));
                for (int i = 0; i < 16; i++) {
                    if ((i & cm) && !(i & tm)) {
                        float tmp = psi[i]; psi[i] = psi[i|tm]; psi[i|tm] = tmp;
                    }
                }
            }
        }
        for (int q = 0; q < NQH; q++) {
            int m = 1 << (NQH-1-q);
            float z = 0.f, xe = 0.f;
            for (int i = 0; i < 16; i++) {
                z  += ((i & m) ? -1.f : 1.f) * psi[i]*psi[i];
                xe += psi[i]*psi[i^m];
            }
            g_attA[t*NQH+q] = z;
            g_attB[t*NQH+q] = -xe;
        }
    }
    if (t == HH) {   // FFN circuit: 8 qubits, 1 layer (ffn_params row 0 only)
        for (int i = 0; i < 256; i++) fpsi[i] = 0.f;
        fpsi[0] = 1.f;
        for (int q = 0; q < NQF; q++) {
            float th = 0.5f * fp[q];
            float c = cosf(th), s = sinf(th);
            int m = 1 << (NQF-1-q);
            for (int i = 0; i < 256; i++) {
                if (!(i & m)) {
                    float a0 = fpsi[i], a1 = fpsi[i|m];
                    fpsi[i]   = c*a0 - s*a1;
                    fpsi[i|m] = s*a0 + c*a1;
                }
            }
        }
        for (int q = 0; q < NQF; q++) {
            int cm = 1 << (NQF-1-q), tm = 1 << (NQF-1-((q+1)%NQF));
            for (int i = 0; i < 256; i++) {
                if ((i & cm) && !(i & tm)) {
                    float tmp = fpsi[i]; fpsi[i] = fpsi[i|tm]; fpsi[i|tm] = tmp;
                }
            }
        }
        for (int q = 0; q < NQF; q++) {
            int m = 1 << (NQF-1-q);
            float z = 0.f, xe = 0.f;
            for (int i = 0; i < 256; i++) {
                z  += ((i & m) ? -1.f : 1.f) * fpsi[i]*fpsi[i];
                xe += fpsi[i]*fpsi[i^m];
            }
            g_ffnA[q] = z;
            g_ffnB[q] = -xe;
        }
    }
}

// ============================================================================
// NT GEMM:  C[M,N] = alpha * A[M,K] * B[N,K]^T   (both row-major, K-contig)
// 64x64x16 tiles, 256 threads, 4x4 microtile. Batched via blockIdx.z strides.
// Requires M,N % 64 == 0, K % 16 == 0 (all shapes here satisfy this).
// ============================================================================
__global__ void __launch_bounds__(256) gemm_nt(
    const float* __restrict__ A, const float* __restrict__ Bw,
    float* __restrict__ C, int M, int N, int K, float alpha,
    size_t sA, size_t sB, size_t sC)
{
    A  += (size_t)blockIdx.z * sA;
    Bw += (size_t)blockIdx.z * sB;
    C  += (size_t)blockIdx.z * sC;
    __shared__ float As[16][64];
    __shared__ float Bs[16][64];
    const int tid = threadIdx.x;
    const int tr = tid >> 4, tc = tid & 15;
    const int row0 = blockIdx.y * 64, col0 = blockIdx.x * 64;
    const int lm = tid >> 2;
    const int lk = (tid & 3) * 4;
    float acc[4][4] = {};
    for (int k0 = 0; k0 < K; k0 += 16) {
        float4 a4 = *(const float4*)(A  + (size_t)(row0 + lm) * K + k0 + lk);
        float4 b4 = *(const float4*)(Bw + (size_t)(col0 + lm) * K + k0 + lk);
        As[lk+0][lm] = a4.x; As[lk+1][lm] = a4.y; As[lk+2][lm] = a4.z; As[lk+3][lm] = a4.w;
        Bs[lk+0][lm] = b4.x; Bs[lk+1][lm] = b4.y; Bs[lk+2][lm] = b4.z; Bs[lk+3][lm] = b4.w;
        __syncthreads();
        #pragma unroll
        for (int kk = 0; kk < 16; kk++) {
            float4 ar = *(const float4*)&As[kk][tr*4];
            float4 br = *(const float4*)&Bs[kk][tc*4];
            float a[4] = {ar.x, ar.y, ar.z, ar.w};
            float b[4] = {br.x, br.y, br.z, br.w};
            #pragma unroll
            for (int i = 0; i < 4; i++)
                #pragma unroll
                for (int j = 0; j < 4; j++)
                    acc[i][j] += a[i]*b[j];
        }
        __syncthreads();
    }
    #pragma unroll
    for (int i = 0; i < 4; i++) {
        float4 o4 = make_float4(alpha*acc[i][0], alpha*acc[i][1],
                                alpha*acc[i][2], alpha*acc[i][3]);
        *(float4*)(C + (size_t)(row0 + tr*4 + i) * N + col0 + tc*4) = o4;
    }
}

// ============================================================================
// NN GEMM:  C[M,N] = A[M,K] * B[K,N]   (row-major). Same tiling.
// ============================================================================
__global__ void __launch_bounds__(256) gemm_nn(
    const float* __restrict__ A, const float* __restrict__ Bw,
    float* __restrict__ C, int M, int N, int K,
    size_t sA, size_t sB, size_t sC)
{
    A  += (size_t)blockIdx.z * sA;
    Bw += (size_t)blockIdx.z * sB;
    C  += (size_t)blockIdx.z * sC;
    __shared__ float As[16][64];
    __shared__ float Bs[16][64];
    const int tid = threadIdx.x;
    const int tr = tid >> 4, tc = tid & 15;
    const int row0 = blockIdx.y * 64, col0 = blockIdx.x * 64;
    const int lm  = tid >> 2;
    const int lk  = (tid & 3) * 4;
    const int lkb = tid >> 4;          // 0..15 (k within tile)
    const int lnn = (tid & 15) * 4;    // 0..60 (n within tile)
    float acc[4][4] = {};
    for (int k0 = 0; k0 < K; k0 += 16) {
        float4 a4 = *(const float4*)(A  + (size_t)(row0 + lm) * K + k0 + lk);
        float4 b4 = *(const float4*)(Bw + (size_t)(k0 + lkb) * N + col0 + lnn);
        As[lk+0][lm] = a4.x; As[lk+1][lm] = a4.y; As[lk+2][lm] = a4.z; As[lk+3][lm] = a4.w;
        *(float4*)&Bs[lkb][lnn] = b4;
        __syncthreads();
        #pragma unroll
        for (int kk = 0; kk < 16; kk++) {
            float4 ar = *(const float4*)&As[kk][tr*4];
            float4 br = *(const float4*)&Bs[kk][tc*4];
            float a[4] = {ar.x, ar.y, ar.z, ar.w};
            float b[4] = {br.x, br.y, br.z, br.w};
            #pragma unroll
            for (int i = 0; i < 4; i++)
                #pragma unroll
                for (int j = 0; j < 4; j++)
                    acc[i][j] += a[i]*b[j];
        }
        __syncthreads();
    }
    #pragma unroll
    for (int i = 0; i < 4; i++) {
        float4 o4 = make_float4(acc[i][0], acc[i][1], acc[i][2], acc[i][3]);
        *(float4*)(C + (size_t)(row0 + tr*4 + i) * N + col0 + tc*4) = o4;
    }
}

// ============================================================================
// Row softmax over T=2048 columns, one block per row.
// ============================================================================
__global__ void __launch_bounds__(256) k_softmax(float* __restrict__ S)
{
    const size_t row = blockIdx.x;
    float* p = S + row * (size_t)TT;
    __shared__ float red[256];
    const int t = threadIdx.x;
    float mx = -1e30f;
    for (int i = t; i < TT; i += 256) mx = fmaxf(mx, p[i]);
    red[t] = mx; __syncthreads();
    for (int st = 128; st > 0; st >>= 1) { if (t < st) red[t] = fmaxf(red[t], red[t+st]); __syncthreads(); }
    mx = red[0]; __syncthreads();
    float sum = 0.f;
    for (int i = t; i < TT; i += 256) { float e = __expf(p[i] - mx); p[i] = e; sum += e; }
    red[t] = sum; __syncthreads();
    for (int st = 128; st > 0; st >>= 1) { if (t < st) red[t] += red[t+st]; __syncthreads(); }
    const float inv = 1.f / red[0];
    for (int i = t; i < TT; i += 256) p[i] *= inv;
}

// ============================================================================
// Fused: quantum head map (closed form) + sparse wo GEMM (32 live columns)
//        + residual + LayerNorm1.  One block per (b,t) row; 256 threads, 2 e each.
// ============================================================================
__global__ void __launch_bounds__(256) k_qattn_ln(
    const float* __restrict__ x, const float* __restrict__ wo,
    const float* __restrict__ g1, const float* __restrict__ b1)
{
    const size_t bt = blockIdx.x;
    __shared__ float qs[32];
    __shared__ float red[256];
    const int t = threadIdx.x;
    if (t < 32) {
        const int h = t >> 2, q = t & 3;
        float u = d_o[bt*EE + h*HD + q];
        qs[t] = g_attA[t]*cosf(u) + g_attB[t]*sinf(u);
    }
    __syncthreads();
    float vals[2];
    #pragma unroll
    for (int r = 0; r < 2; r++) {
        const int e = t + r*256;
        float acc = 0.f;
        #pragma unroll
        for (int j = 0; j < 32; j++)
            acc += qs[j] * wo[(size_t)e*EE + (j>>2)*HD + (j&3)];
        vals[r] = x[bt*EE + e] + acc;
    }
    red[t] = vals[0] + vals[1]; __syncthreads();
    for (int st = 128; st > 0; st >>= 1) { if (t < st) red[t] += red[t+st]; __syncthreads(); }
    const float mean = red[0] * (1.f/EE);
    __syncthreads();
    float dv0 = vals[0]-mean, dv1 = vals[1]-mean;
    red[t] = dv0*dv0 + dv1*dv1; __syncthreads();
    for (int st = 128; st > 0; st >>= 1) { if (t < st) red[t] += red[t+st]; __syncthreads(); }
    const float rstd = rsqrtf(red[0]*(1.f/EE) + 1e-5f);
    #pragma unroll
    for (int r = 0; r < 2; r++) {
        const int e = t + r*256;
        d_x1[bt*EE + e] = (vals[r]-mean)*rstd*g1[e] + b1[e];
    }
}

// ============================================================================
// Fused: FFN quantum map (closed form on x1[:, :8]) + w1 GEMV + ReLU -> h1
// ============================================================================
__global__ void __launch_bounds__(256) k_ffn_h1(const float* __restrict__ w1)
{
    const size_t bt = blockIdx.x;
    __shared__ float f8[8];
    const int t = threadIdx.x;
    if (t < 8) {
        float u = d_x1[bt*EE + t];
        f8[t] = g_ffnA[t]*cosf(u) + g_ffnB[t]*sinf(u);
    }
    __syncthreads();
    for (int f = t; f < FFND; f += 256) {
        float acc = 0.f;
        #pragma unroll
        for (int q = 0; q < 8; q++) acc += f8[q] * w1[f*8 + q];
        d_h1[bt*FFND + f] = fmaxf(acc, 0.f);
    }
}

// ============================================================================
// Final: out = LayerNorm2(x1 + f)
// ============================================================================
__global__ void __launch_bounds__(256) k_final(
    const float* __restrict__ g2, const float* __restrict__ b2,
    float* __restrict__ out)
{
    const size_t bt = blockIdx.x;
    __shared__ float red[256];
    const int t = threadIdx.x;
    float vals[2];
    #pragma unroll
    for (int r = 0; r < 2; r++) {
        const int e = t + r*256;
        vals[r] = d_x1[bt*EE + e] + d_f[bt*EE + e];
    }
    red[t] = vals[0] + vals[1]; __syncthreads();
    for (int st = 128; st > 0; st >>= 1) { if (t < st) red[t] += red[t+st]; __syncthreads(); }
    const float mean = red[0] * (1.f/EE);
    __syncthreads();
    float dv0 = vals[0]-mean, dv1 = vals[1]-mean;
    red[t] = dv0*dv0 + dv1*dv1; __syncthreads();
    for (int st = 128; st > 0; st >>= 1) { if (t < st) red[t] += red[t+st]; __syncthreads(); }
    const float rstd = rsqrtf(red[0]*(1.f/EE) + 1e-5f);
    #pragma unroll
    for (int r = 0; r < 2; r++) {
        const int e = t + r*256;
        out[bt*EE + e] = (vals[r]-mean)*rstd*g2[e] + b2[e];
    }
}

// ============================================================================
extern "C" void kernel_launch(void* const* d_in, const int* in_sizes, int n_in,
                              void* d_out, int out_size)
{
    const float* x  = (const float*)d_in[0];
    const float* wq = (const float*)d_in[1];
    const float* wk = (const float*)d_in[2];
    const float* wv = (const float*)d_in[3];
    const float* wo = (const float*)d_in[4];
    const float* hp = (const float*)d_in[5];
    const float* fp = (const float*)d_in[6];
    const float* w1 = (const float*)d_in[7];
    const float* w2 = (const float*)d_in[8];
    const float* g1 = (const float*)d_in[9];
    const float* b1 = (const float*)d_in[10];
    const float* g2 = (const float*)d_in[11];
    const float* b2 = (const float*)d_in[12];
    float* out = (float*)d_out;

    float *pq, *pk, *pv, *ps, *po, *ph1, *pf;
    cudaGetSymbolAddress((void**)&pq,  d_q);
    cudaGetSymbolAddress((void**)&pk,  d_k);
    cudaGetSymbolAddress((void**)&pv,  d_v);
    cudaGetSymbolAddress((void**)&ps,  d_s);
    cudaGetSymbolAddress((void**)&po,  d_o);
    cudaGetSymbolAddress((void**)&ph1, d_h1);
    cudaGetSymbolAddress((void**)&pf,  d_f);

    // 0) circuit constants (tiny)
    k_circuits<<<1, 32>>>(hp, fp);

    // 1) QKV projections: [BT,E] x [E,E]^T
    {
        dim3 grid(EE/64, BTN/64, 1);
        gemm_nt<<<grid, 256>>>(x, wq, pq, BTN, EE, EE, 1.f, 0, 0, 0);
        gemm_nt<<<grid, 256>>>(x, wk, pk, BTN, EE, EE, 1.f, 0, 0, 0);
        gemm_nt<<<grid, 256>>>(x, wv, pv, BTN, EE, EE, 1.f, 0, 0, 0);
    }

    // 2) scores = q @ k^T / sqrt(E), batched over B
    {
        dim3 grid(TT/64, TT/64, BB);
        gemm_nt<<<grid, 256>>>(pq, pk, ps, TT, TT, EE, 0.044194173824159216f,
                               (size_t)TT*EE, (size_t)TT*EE, (size_t)TT*TT);
    }

    // 3) softmax rows
    k_softmax<<<BTN, 256>>>(ps);

    // 4) out = attn @ v, batched over B
    {
        dim3 grid(EE/64, TT/64, BB);
        gemm_nn<<<grid, 256>>>(ps, pv, po, TT, EE, TT,
                               (size_t)TT*TT, (size_t)TT*EE, (size_t)TT*EE);
    }

    // 5) quantum head map + wo + residual + LN1 -> x1
    k_qattn_ln<<<BTN, 256>>>(x, wo, g1, b1);

    // 6) FFN quantum map + w1 + ReLU -> h1
    k_ffn_h1<<<BTN, 256>>>(w1);

    // 7) f = h1 @ w2^T
    {
        dim3 grid(EE/64, BTN/64, 1);
        gemm_nt<<<grid, 256>>>(ph1, w2, pf, BTN, EE, FFND, 1.f, 0, 0, 0);
    }

    // 8) out = LN2(x1 + f)
    k_final<<<BTN, 256>>>(g2, b2, out);
}

// round 7
// speedup vs baseline: 4.0735x; 4.0735x over previous
#include <cuda_runtime.h>
#include <cstdint>
#include <math.h>

#define BB   8
#define TT   2048
#define EE   512
#define HH   8
#define HD   64
#define NQH  4
#define NLAY 2
#define NQF  8
#define FFND 2048
#define BTN  (BB*TT)

// ---- GEMM tiling ----
#define NSTAGE 3
#define KTILE  32
#define TILEF  (128*32)            // floats per matrix tile per stage
#define STAGEF (2*TILEF)           // A+B
#define SMEM_DYN (NSTAGE*STAGEF*4) // 98304 bytes

// ---- scratch (static device globals; no allocation allowed) ----
static __device__ float d_q  [(size_t)BTN*EE];
static __device__ float d_k  [(size_t)BTN*EE];
static __device__ float d_v  [(size_t)BTN*EE];
static __device__ float d_vT [(size_t)BTN*EE];
static __device__ float d_s  [(size_t)BB*TT*TT];
static __device__ float d_o  [(size_t)BTN*EE];
static __device__ float d_q32[(size_t)BTN*32];
static __device__ float d_woc[(size_t)EE*32];
static __device__ float d_att[(size_t)BTN*EE];
static __device__ float d_x1 [(size_t)BTN*EE];
static __device__ float d_f8 [(size_t)BTN*32];
static __device__ float d_w1p[(size_t)FFND*32];
static __device__ float d_h1 [(size_t)BTN*FFND];
static __device__ float d_f  [(size_t)BTN*EE];
static __device__ float g_attA[32], g_attB[32], g_ffnA[8], g_ffnB[8];

// ============================ helpers =======================================
__device__ __forceinline__ uint32_t smem_u32(const void* p) {
    uint32_t a;
    asm("{ .reg .u64 t; cvta.to.shared.u64 t, %1; cvt.u32.u64 %0, t; }" : "=r"(a) : "l"(p));
    return a;
}
__device__ __forceinline__ uint32_t f2tf(float x) {
    uint32_t u;
    asm("cvt.rna.tf32.f32 %0, %1;" : "=r"(u) : "f"(x));
    return u;
}
__device__ __forceinline__ void mma8(float* d, const uint32_t* a, uint32_t b0, uint32_t b1) {
    asm volatile(
        "mma.sync.aligned.m16n8k8.row.col.f32.tf32.tf32.f32 "
        "{%0,%1,%2,%3}, {%4,%5,%6,%7}, {%8,%9}, {%0,%1,%2,%3};"
        : "+f"(d[0]), "+f"(d[1]), "+f"(d[2]), "+f"(d[3])
        : "r"(a[0]), "r"(a[1]), "r"(a[2]), "r"(a[3]), "r"(b0), "r"(b1));
}
// fill one 128x32 tile stage: cp.async 16B chunks, chunk-XOR swizzle
__device__ __forceinline__ void stage_load(
    float* dst, const float* src, int K, int k0, int tid)
{
    #pragma unroll
    for (int r = 0; r < 4; r++) {
        int id  = tid + r*256;
        int row = id >> 3, ch = id & 7;
        int chp = ch ^ (row & 7);
        uint32_t da = smem_u32(dst + row*32 + chp*4);
        const float* gp = src + (size_t)row * K + k0 + ch*4;
        asm volatile("cp.async.cg.shared.global [%0], [%1], 16;"
                     :: "r"(da), "l"(gp) : "memory");
    }
}

// ============================================================================
// tf32 mma.sync NT GEMM: C[M,N] = act(alpha * A[M,K] * B[N,K]^T)
// CTA 128x128, 8 warps (2m x 4n), warp tile 64x32, 3-stage cp.async pipeline.
// M,N % 128 == 0, K % 32 == 0 (all call sites satisfy this).
// K-permuted fragments: logical mma col t <-> phys k 2t, t+4 <-> 2t+1,
// applied identically to A and B (sum over k is permutation-invariant),
// so every fragment load is one float2.
// ============================================================================
__global__ void __launch_bounds__(256) gemm_mma(
    const float* __restrict__ A, const float* __restrict__ Bm, float* __restrict__ C,
    int M, int N, int K, float alpha, int relu,
    size_t sA, size_t sB, size_t sC)
{
    extern __shared__ float sm[];
    A  += (size_t)blockIdx.z * sA;
    Bm += (size_t)blockIdx.z * sB;
    C  += (size_t)blockIdx.z * sC;

    const int tid = threadIdx.x, wid = tid >> 5, lane = tid & 31;
    const int g = lane >> 2, t = lane & 3;
    const int row0 = blockIdx.y * 128, col0 = blockIdx.x * 128;
    const int m0w = (wid >> 2) * 64;     // 0 or 64
    const int n0w = (wid & 3) * 32;      // 0,32,64,96
    const int KT = K >> 5;

    const float* Abase = A  + (size_t)row0 * K;
    const float* Bbase = Bm + (size_t)col0 * K;

    // ---- prologue: stages 0..NSTAGE-2 ----
    #pragma unroll
    for (int s = 0; s < NSTAGE-1; s++) {
        if (s < KT) {
            stage_load(sm + s*STAGEF,         Abase, K, s*KTILE, tid);
            stage_load(sm + s*STAGEF + TILEF, Bbase, K, s*KTILE, tid);
        }
        asm volatile("cp.async.commit_group;" ::: "memory");
    }

    float acc[4][4][4] = {};   // [mi][nj][4]

    for (int kt = 0; kt < KT; kt++) {
        asm volatile("cp.async.wait_group %0;" :: "n"(NSTAGE-2) : "memory");
        __syncthreads();

        // prefetch stage kt+NSTAGE-1 into the buffer just freed
        const int pf = kt + NSTAGE - 1;
        if (pf < KT) {
            const int s = pf % NSTAGE;
            stage_load(sm + s*STAGEF,         Abase, K, pf*KTILE, tid);
            stage_load(sm + s*STAGEF + TILEF, Bbase, K, pf*KTILE, tid);
        }
        asm volatile("cp.async.commit_group;" ::: "memory");

        const float* As = sm + (kt % NSTAGE) * STAGEF;
        const float* Bs = As + TILEF;

        #pragma unroll
        for (int ks = 0; ks < 4; ks++) {
            const int chunk = ks*2 + (t >> 1);
            const int offl  = (t & 1) * 2;
            uint32_t afr[4][4];
            #pragma unroll
            for (int mi = 0; mi < 4; mi++) {
                const int rlo = m0w + mi*16 + g;
                const int rhi = rlo + 8;
                float2 lo = *(const float2*)(As + rlo*32 + (chunk ^ (rlo & 7))*4 + offl);
                float2 hi = *(const float2*)(As + rhi*32 + (chunk ^ (rhi & 7))*4 + offl);
                afr[mi][0] = f2tf(lo.x); afr[mi][1] = f2tf(hi.x);
                afr[mi][2] = f2tf(lo.y); afr[mi][3] = f2tf(hi.y);
            }
            #pragma unroll
            for (int nj = 0; nj < 4; nj++) {
                const int rb = n0w + nj*8 + g;
                float2 bp = *(const float2*)(Bs + rb*32 + (chunk ^ (rb & 7))*4 + offl);
                const uint32_t b0 = f2tf(bp.x), b1 = f2tf(bp.y);
                #pragma unroll
                for (int mi = 0; mi < 4; mi++)
                    mma8(acc[mi][nj], afr[mi], b0, b1);
            }
        }
    }

    // ---- epilogue ----
    #pragma unroll
    for (int mi = 0; mi < 4; mi++) {
        const int r = row0 + m0w + mi*16 + g;
        #pragma unroll
        for (int nj = 0; nj < 4; nj++) {
            const int c = col0 + n0w + nj*8 + 2*t;
            float2 v0, v1;
            v0.x = alpha * acc[mi][nj][0]; v0.y = alpha * acc[mi][nj][1];
            v1.x = alpha * acc[mi][nj][2]; v1.y = alpha * acc[mi][nj][3];
            if (relu) {
                v0.x = fmaxf(v0.x, 0.f); v0.y = fmaxf(v0.y, 0.f);
                v1.x = fmaxf(v1.x, 0.f); v1.y = fmaxf(v1.y, 0.f);
            }
            *(float2*)(C + (size_t)r     * N + c) = v0;
            *(float2*)(C + (size_t)(r+8) * N + c) = v1;
        }
    }
}

// ============================================================================
// Tiny kernel: parameter-only circuit sims -> (A,B) closed-form constants
// ============================================================================
__global__ void k_circuits(const float* __restrict__ hp, const float* __restrict__ fp)
{
    __shared__ float fpsi[256];
    const int t = threadIdx.x;
    if (t < HH) {
        float psi[16];
        #pragma unroll
        for (int i = 0; i < 16; i++) psi[i] = 0.f;
        psi[0] = 1.f;
        for (int l = 0; l < NLAY; l++) {
            for (int q = 0; q < NQH; q++) {
                float th = 0.5f * hp[t*NLAY*NQH + l*NQH + q];
                float c = cosf(th), s = sinf(th);
                int m = 1 << (NQH-1-q);
                for (int i = 0; i < 16; i++)
                    if (!(i & m)) {
                        float a0 = psi[i], a1 = psi[i|m];
                        psi[i] = c*a0 - s*a1; psi[i|m] = s*a0 + c*a1;
                    }
            }
            for (int q = 0; q < NQH; q++) {
                int cm = 1 << (NQH-1-q), tm = 1 << (NQH-1-((q+1)%NQH));
                for (int i = 0; i < 16; i++)
                    if ((i & cm) && !(i & tm)) {
                        float tmp = psi[i]; psi[i] = psi[i|tm]; psi[i|tm] = tmp;
                    }
            }
        }
        for (int q = 0; q < NQH; q++) {
            int m = 1 << (NQH-1-q);
            float z = 0.f, xe = 0.f;
            for (int i = 0; i < 16; i++) {
                z  += ((i & m) ? -1.f : 1.f) * psi[i]*psi[i];
                xe += psi[i]*psi[i^m];
            }
            g_attA[t*NQH+q] = z; g_attB[t*NQH+q] = -xe;
        }
    }
    if (t == HH) {
        for (int i = 0; i < 256; i++) fpsi[i] = 0.f;
        fpsi[0] = 1.f;
        for (int q = 0; q < NQF; q++) {
            float th = 0.5f * fp[q];
            float c = cosf(th), s = sinf(th);
            int m = 1 << (NQF-1-q);
            for (int i = 0; i < 256; i++)
                if (!(i & m)) {
                    float a0 = fpsi[i], a1 = fpsi[i|m];
                    fpsi[i] = c*a0 - s*a1; fpsi[i|m] = s*a0 + c*a1;
                }
        }
        for (int q = 0; q < NQF; q++) {
            int cm = 1 << (NQF-1-q), tm = 1 << (NQF-1-((q+1)%NQF));
            for (int i = 0; i < 256; i++)
                if ((i & cm) && !(i & tm)) {
                    float tmp = fpsi[i]; fpsi[i] = fpsi[i|tm]; fpsi[i|tm] = tmp;
                }
        }
        for (int q = 0; q < NQF; q++) {
            int m = 1 << (NQF-1-q);
            float z = 0.f, xe = 0.f;
            for (int i = 0; i < 256; i++) {
                z  += ((i & m) ? -1.f : 1.f) * fpsi[i]*fpsi[i];
                xe += fpsi[i]*fpsi[i^m];
            }
            g_ffnA[q] = z; g_ffnB[q] = -xe;
        }
    }
}

// ---- V transpose: d_vT[b][e][t] = d_v[b][t][e] -----------------------------
__global__ void k_vtrans()
{
    __shared__ float tile[32][33];
    const int b = blockIdx.z;
    const int t0 = blockIdx.x*32, e0 = blockIdx.y*32;
    const int tx = threadIdx.x, ty = threadIdx.y;        // (32, 8)
    const float* vp = d_v  + (size_t)b*TT*EE;
    float*       op = d_vT + (size_t)b*EE*TT;
    #pragma unroll
    for (int i = 0; i < 32; i += 8)
        tile[ty+i][tx] = vp[(size_t)(t0+ty+i)*EE + e0+tx];
    __syncthreads();
    #pragma unroll
    for (int i = 0; i < 32; i += 8)
        op[(size_t)(e0+ty+i)*TT + t0+tx] = tile[tx][ty+i];
}

// ---- 2-read softmax over rows of 2048 --------------------------------------
__global__ void __launch_bounds__(256) k_softmax(float* __restrict__ S)
{
    const size_t row = blockIdx.x;
    float4* p = (float4*)(S + row*(size_t)TT);
    const int t = threadIdx.x;
    __shared__ float red[256];
    float4 x0 = p[t], x1 = p[t + 256];
    float m = fmaxf(fmaxf(fmaxf(x0.x,x0.y), fmaxf(x0.z,x0.w)),
                    fmaxf(fmaxf(x1.x,x1.y), fmaxf(x1.z,x1.w)));
    red[t] = m; __syncthreads();
    for (int st = 128; st > 0; st >>= 1) { if (t < st) red[t] = fmaxf(red[t], red[t+st]); __syncthreads(); }
    m = red[0]; __syncthreads();
    float4 e0, e1;
    e0.x = __expf(x0.x - m); e0.y = __expf(x0.y - m); e0.z = __expf(x0.z - m); e0.w = __expf(x0.w - m);
    e1.x = __expf(x1.x - m); e1.y = __expf(x1.y - m); e1.z = __expf(x1.z - m); e1.w = __expf(x1.w - m);
    red[t] = e0.x+e0.y+e0.z+e0.w + e1.x+e1.y+e1.z+e1.w; __syncthreads();
    for (int st = 128; st > 0; st >>= 1) { if (t < st) red[t] += red[t+st]; __syncthreads(); }
    const float inv = 1.f / red[0];
    e0.x *= inv; e0.y *= inv; e0.z *= inv; e0.w *= inv;
    e1.x *= inv; e1.y *= inv; e1.z *= inv; e1.w *= inv;
    p[t] = e0; p[t + 256] = e1;
}

// ---- quantum head map: Q32[bt][j] = A_j cos(u) + B_j sin(u) ----------------
__global__ void k_qmap(float* __restrict__ q32)
{
    const int idx = blockIdx.x*256 + threadIdx.x;    // BTN*32
    const int bt = idx >> 5, j = idx & 31;
    const float u = d_o[(size_t)bt*EE + (j>>2)*HD + (j&3)];
    q32[idx] = g_attA[j]*cosf(u) + g_attB[j]*sinf(u);
}

// ---- compact wo: woc[e][j] = wo[e][(j>>2)*64 + (j&3)] ----------------------
__global__ void k_woc(const float* __restrict__ wo, float* __restrict__ woc)
{
    const int idx = blockIdx.x*256 + threadIdx.x;    // EE*32
    const int e = idx >> 5, j = idx & 31;
    woc[idx] = wo[(size_t)e*EE + (j>>2)*HD + (j&3)];
}

// ---- pad w1 [2048,8] -> [2048,32] ------------------------------------------
__global__ void k_w1pad(const float* __restrict__ w1, float* __restrict__ w1p)
{
    const int idx = blockIdx.x*256 + threadIdx.x;    // FFND*32
    const int f = idx >> 5, j = idx & 31;
    w1p[idx] = (j < 8) ? w1[f*8 + j] : 0.f;
}

// ---- FFN quantum map (padded to K=32) --------------------------------------
__global__ void k_f8(float* __restrict__ f8p)
{
    const int idx = blockIdx.x*256 + threadIdx.x;    // BTN*32
    const int bt = idx >> 5, j = idx & 31;
    float r = 0.f;
    if (j < 8) {
        const float u = d_x1[(size_t)bt*EE + j];
        r = g_ffnA[j]*cosf(u) + g_ffnB[j]*sinf(u);
    }
    f8p[idx] = r;
}

// ---- generic residual LayerNorm: out = LN(a + c) ---------------------------
__global__ void __launch_bounds__(256) k_ln(
    const float* __restrict__ a, const float* __restrict__ c,
    const float* __restrict__ g, const float* __restrict__ bb, float* __restrict__ out)
{
    const size_t bt = blockIdx.x;
    __shared__ float red[256];
    const int t = threadIdx.x;
    float v0 = a[bt*EE + t]       + c[bt*EE + t];
    float v1 = a[bt*EE + t + 256] + c[bt*EE + t + 256];
    red[t] = v0 + v1; __syncthreads();
    for (int st = 128; st > 0; st >>= 1) { if (t < st) red[t] += red[t+st]; __syncthreads(); }
    const float mean = red[0] * (1.f/EE);
    __syncthreads();
    float d0 = v0 - mean, d1 = v1 - mean;
    red[t] = d0*d0 + d1*d1; __syncthreads();
    for (int st = 128; st > 0; st >>= 1) { if (t < st) red[t] += red[t+st]; __syncthreads(); }
    const float rstd = rsqrtf(red[0]*(1.f/EE) + 1e-5f);
    out[bt*EE + t]       = d0*rstd*g[t]     + bb[t];
    out[bt*EE + t + 256] = d1*rstd*g[t+256] + bb[t+256];
}

// ============================================================================
extern "C" void kernel_launch(void* const* d_in, const int* in_sizes, int n_in,
                              void* d_out, int out_size)
{
    const float* x  = (const float*)d_in[0];
    const float* wq = (const float*)d_in[1];
    const float* wk = (const float*)d_in[2];
    const float* wv = (const float*)d_in[3];
    const float* wo = (const float*)d_in[4];
    const float* hp = (const float*)d_in[5];
    const float* fp = (const float*)d_in[6];
    const float* w1 = (const float*)d_in[7];
    const float* w2 = (const float*)d_in[8];
    const float* g1 = (const float*)d_in[9];
    const float* b1 = (const float*)d_in[10];
    const float* g2 = (const float*)d_in[11];
    const float* b2 = (const float*)d_in[12];
    float* out = (float*)d_out;

    cudaFuncSetAttribute(gemm_mma, cudaFuncAttributeMaxDynamicSharedMemorySize, SMEM_DYN);

    float *pq, *pk, *pv, *pvT, *ps, *po, *pq32, *pwoc, *patt, *px1, *pf8, *pw1p, *ph1, *pf;
    cudaGetSymbolAddress((void**)&pq,   d_q);
    cudaGetSymbolAddress((void**)&pk,   d_k);
    cudaGetSymbolAddress((void**)&pv,   d_v);
    cudaGetSymbolAddress((void**)&pvT,  d_vT);
    cudaGetSymbolAddress((void**)&ps,   d_s);
    cudaGetSymbolAddress((void**)&po,   d_o);
    cudaGetSymbolAddress((void**)&pq32, d_q32);
    cudaGetSymbolAddress((void**)&pwoc, d_woc);
    cudaGetSymbolAddress((void**)&patt, d_att);
    cudaGetSymbolAddress((void**)&px1,  d_x1);
    cudaGetSymbolAddress((void**)&pf8,  d_f8);
    cudaGetSymbolAddress((void**)&pw1p, d_w1p);
    cudaGetSymbolAddress((void**)&ph1,  d_h1);
    cudaGetSymbolAddress((void**)&pf,   d_f);

    // constants / weight preps
    k_circuits<<<1, 32>>>(hp, fp);
    k_woc<<<(EE*32)/256, 256>>>(wo, pwoc);
    k_w1pad<<<(FFND*32)/256, 256>>>(w1, pw1p);

    // QKV projections
    {
        dim3 g(EE/128, BTN/128, 1);
        gemm_mma<<<g, 256, SMEM_DYN>>>(x, wq, pq, BTN, EE, EE, 1.f, 0, 0, 0, 0);
        gemm_mma<<<g, 256, SMEM_DYN>>>(x, wk, pk, BTN, EE, EE, 1.f, 0, 0, 0, 0);
        gemm_mma<<<g, 256, SMEM_DYN>>>(x, wv, pv, BTN, EE, EE, 1.f, 0, 0, 0, 0);
    }
    // V transpose for NT attn@V
    {
        dim3 g(TT/32, EE/32, BB);
        k_vtrans<<<g, dim3(32, 8)>>>();
    }
    // scores = q k^T / sqrt(E)
    {
        dim3 g(TT/128, TT/128, BB);
        gemm_mma<<<g, 256, SMEM_DYN>>>(pq, pk, ps, TT, TT, EE, 0.044194173824159216f, 0,
                                       (size_t)TT*EE, (size_t)TT*EE, (size_t)TT*TT);
    }
    k_softmax<<<BTN, 256>>>(ps);
    // o = attn @ v  (NT against vT)
    {
        dim3 g(EE/128, TT/128, BB);
        gemm_mma<<<g, 256, SMEM_DYN>>>(ps, pvT, po, TT, EE, TT, 1.f, 0,
                                       (size_t)TT*TT, (size_t)EE*TT, (size_t)TT*EE);
    }
    // quantum head map, wo projection, LN1
    k_qmap<<<(BTN*32)/256, 256>>>(pq32);
    {
        dim3 g(EE/128, BTN/128, 1);
        gemm_mma<<<g, 256, SMEM_DYN>>>(pq32, pwoc, patt, BTN, EE, 32, 1.f, 0, 0, 0, 0);
    }
    k_ln<<<BTN, 256>>>(x, patt, g1, b1, px1);
    // FFN: quantum map -> w1 (relu) -> w2
    k_f8<<<(BTN*32)/256, 256>>>(pf8);
    {
        dim3 g(FFND/128, BTN/128, 1);
        gemm_mma<<<g, 256, SMEM_DYN>>>(pf8, pw1p, ph1, BTN, FFND, 32, 1.f, 1, 0, 0, 0);
    }
    {
        dim3 g(EE/128, BTN/128, 1);
        gemm_mma<<<g, 256, SMEM_DYN>>>(ph1, w2, pf, BTN, EE, FFND, 1.f, 0, 0, 0, 0);
    }
    k_ln<<<BTN, 256>>>(px1, pf, g2, b2, out);
}

// round 9
// speedup vs baseline: 5.7904x; 1.4215x over previous
#include <cuda_runtime.h>
#include <cstdint>
#include <math.h>

#define BB   8
#define TT   2048
#define EE   512
#define HH   8
#define HD   64
#define NQH  4
#define NLAY 2
#define NQF  8
#define FFND 2048
#define BTN  (BB*TT)
#define NQKV 1152              // 512 q + 512 k + 32 v_compact + 96 pad

#define NSTAGE 3
#define KTILE  32

// ---- scratch (static device globals; no allocation allowed) ----
static __device__ float d_xr  [(size_t)BTN*EE];
static __device__ float d_wqkv[(size_t)NQKV*EE];
static __device__ float d_qkv [(size_t)BTN*NQKV];
static __device__ float d_vTc [(size_t)BB*32*TT];
static __device__ float d_s   [(size_t)BB*TT*TT];
static __device__ float d_o   [(size_t)BTN*32];
static __device__ float d_q32 [(size_t)BTN*32];
static __device__ float d_woc [(size_t)EE*32];
static __device__ float d_att [(size_t)BTN*EE];
static __device__ float d_x1  [(size_t)BTN*EE];
static __device__ float d_f8  [(size_t)BTN*32];
static __device__ float d_w1p [(size_t)FFND*32];
static __device__ float d_w2r [(size_t)EE*FFND];
static __device__ float d_h1  [(size_t)BTN*FFND];
static __device__ float d_f   [(size_t)BTN*EE];
static __device__ float g_attA[32], g_attB[32], g_ffnA[8], g_ffnB[8];

// ============================ helpers =======================================
__device__ __forceinline__ uint32_t smem_u32(const void* p) {
    uint32_t a;
    asm("{ .reg .u64 t; cvta.to.shared.u64 t, %1; cvt.u32.u64 %0, t; }" : "=r"(a) : "l"(p));
    return a;
}
__device__ __forceinline__ float f2tf(float x) {       // round-to-nearest tf32, as float bits
    uint32_t u;
    asm("cvt.rna.tf32.f32 %0, %1;" : "=r"(u) : "f"(x));
    return __uint_as_float(u);
}
__device__ __forceinline__ void mma8(float* d,
    uint32_t a0, uint32_t a1, uint32_t a2, uint32_t a3, uint32_t b0, uint32_t b1)
{
    asm volatile(
        "mma.sync.aligned.m16n8k8.row.col.f32.tf32.tf32.f32 "
        "{%0,%1,%2,%3}, {%4,%5,%6,%7}, {%8,%9}, {%0,%1,%2,%3};"
        : "+f"(d[0]), "+f"(d[1]), "+f"(d[2]), "+f"(d[3])
        : "r"(a0), "r"(a1), "r"(a2), "r"(a3), "r"(b0), "r"(b1));
}

// ============================================================================
// tf32 mma.sync NT GEMM: C[M,N] = act(alpha * A[M,K] * B[N,K]^T)
// CTA tile 128 x BN (BN = 128 or 32), 8 warps, 3-stage cp.async pipeline.
// Inputs are assumed tf32-prerounded (raw bits fed to MMA; HW reads bits[31:13]).
// K-permutation: per 32-k tile, thread quad-lane t loads chunk (2t+h), h=0,1,
// giving 2 mma k-steps per float4; identical permutation on A and B.
// Swizzle chunk^(row&7) -> conflict-free LDS.128 and cp.async stores.
// M % 128 == 0, N % BN == 0, K % 32 == 0.
// ============================================================================
template<int BN>
__global__ void __launch_bounds__(256, 2) gemm_mma(
    const float* __restrict__ A, const float* __restrict__ Bm, float* __restrict__ C,
    int M, int N, int K, int lda, int ldb, int ldc,
    float alpha, int relu, int rnd,
    size_t sA, size_t sB, size_t sC)
{
    constexpr int NWN = BN/32;          // warps along n
    constexpr int NWM = 8/NWN;          // warps along m
    constexpr int MI  = (128/NWM)/16;   // 16-row mma tiles per warp
    constexpr int TA  = 128*32;         // A tile floats
    constexpr int TB  = BN*32;          // B tile floats
    constexpr int SF  = TA + TB;        // floats per stage

    extern __shared__ float sm[];
    A  += (size_t)blockIdx.z * sA;
    Bm += (size_t)blockIdx.z * sB;
    C  += (size_t)blockIdx.z * sC;

    const int tid = threadIdx.x, wid = tid >> 5, lane = tid & 31;
    const int g = lane >> 2, t = lane & 3;
    const int row0 = blockIdx.y * 128, col0 = blockIdx.x * BN;
    const int m0w = (wid / NWN) * (MI*16);
    const int n0w = (wid % NWN) * 32;
    const int KT = K >> 5;

    const float* Ab = A  + (size_t)row0 * lda;
    const float* Bb = Bm + (size_t)col0 * ldb;

    auto load_stage = [&](int s, int k0) {
        #pragma unroll
        for (int r = 0; r < 4; r++) {                       // A: 128 rows
            int id = tid + r*256;
            int row = id >> 3, ch = id & 7, chp = ch ^ (row & 7);
            uint32_t da = smem_u32(sm + s*SF + row*32 + chp*4);
            asm volatile("cp.async.cg.shared.global [%0], [%1], 16;"
                         :: "r"(da), "l"(Ab + (size_t)row*lda + k0 + ch*4) : "memory");
        }
        #pragma unroll
        for (int r = 0; r < BN/32; r++) {                   // B: BN rows
            int id = tid + r*256;
            int row = id >> 3, ch = id & 7, chp = ch ^ (row & 7);
            uint32_t da = smem_u32(sm + s*SF + TA + row*32 + chp*4);
            asm volatile("cp.async.cg.shared.global [%0], [%1], 16;"
                         :: "r"(da), "l"(Bb + (size_t)row*ldb + k0 + ch*4) : "memory");
        }
    };

    // ---- prologue ----
    #pragma unroll
    for (int s = 0; s < NSTAGE-1; s++) {
        if (s < KT) load_stage(s, s*KTILE);
        asm volatile("cp.async.commit_group;" ::: "memory");
    }

    float acc[MI][4][4] = {};

    for (int kt = 0; kt < KT; kt++) {
        asm volatile("cp.async.wait_group %0;" :: "n"(NSTAGE-2) : "memory");
        __syncthreads();

        const int pf = kt + NSTAGE - 1;
        if (pf < KT) load_stage(pf % NSTAGE, pf*KTILE);
        asm volatile("cp.async.commit_group;" ::: "memory");

        const float* As = sm + (kt % NSTAGE) * SF;
        const float* Bs = As + TA;

        #pragma unroll
        for (int h = 0; h < 2; h++) {
            float4 av[MI][2];
            #pragma unroll
            for (int mi = 0; mi < MI; mi++) {
                const int rlo = m0w + mi*16 + g, rhi = rlo + 8;
                av[mi][0] = *(const float4*)(As + rlo*32 + ((2*t+h) ^ (rlo & 7))*4);
                av[mi][1] = *(const float4*)(As + rhi*32 + ((2*t+h) ^ (rhi & 7))*4);
            }
            #pragma unroll
            for (int nj = 0; nj < 4; nj++) {
                const int rb = n0w + nj*8 + g;
                float4 bv = *(const float4*)(Bs + rb*32 + ((2*t+h) ^ (rb & 7))*4);
                const uint32_t b0 = __float_as_uint(bv.x), b1 = __float_as_uint(bv.y);
                const uint32_t b2 = __float_as_uint(bv.z), b3 = __float_as_uint(bv.w);
                #pragma unroll
                for (int mi = 0; mi < MI; mi++) {
                    mma8(acc[mi][nj],
                         __float_as_uint(av[mi][0].x), __float_as_uint(av[mi][1].x),
                         __float_as_uint(av[mi][0].y), __float_as_uint(av[mi][1].y), b0, b1);
                    mma8(acc[mi][nj],
                         __float_as_uint(av[mi][0].z), __float_as_uint(av[mi][1].z),
                         __float_as_uint(av[mi][0].w), __float_as_uint(av[mi][1].w), b2, b3);
                }
            }
        }
    }

    // ---- epilogue ----
    #pragma unroll
    for (int mi = 0; mi < MI; mi++) {
        const int r = row0 + m0w + mi*16 + g;
        #pragma unroll
        for (int nj = 0; nj < 4; nj++) {
            const int c = col0 + n0w + nj*8 + 2*t;
            float2 v0, v1;
            v0.x = alpha * acc[mi][nj][0]; v0.y = alpha * acc[mi][nj][1];
            v1.x = alpha * acc[mi][nj][2]; v1.y = alpha * acc[mi][nj][3];
            if (relu) {
                v0.x = fmaxf(v0.x, 0.f); v0.y = fmaxf(v0.y, 0.f);
                v1.x = fmaxf(v1.x, 0.f); v1.y = fmaxf(v1.y, 0.f);
            }
            if (rnd) {
                v0.x = f2tf(v0.x); v0.y = f2tf(v0.y);
                v1.x = f2tf(v1.x); v1.y = f2tf(v1.y);
            }
            *(float2*)(C + (size_t)r     * ldc + c) = v0;
            *(float2*)(C + (size_t)(r+8) * ldc + c) = v1;
        }
    }
}

// ============================================================================
// Parameter-only circuit sims -> closed-form (A,B): qout = A cos(u) + B sin(u)
// ============================================================================
__global__ void k_circuits(const float* __restrict__ hp, const float* __restrict__ fp)
{
    __shared__ float fpsi[256];
    const int t = threadIdx.x;
    if (t < HH) {
        float psi[16];
        #pragma unroll
        for (int i = 0; i < 16; i++) psi[i] = 0.f;
        psi[0] = 1.f;
        for (int l = 0; l < NLAY; l++) {
            for (int q = 0; q < NQH; q++) {
                float th = 0.5f * hp[t*NLAY*NQH + l*NQH + q];
                float c = cosf(th), s = sinf(th);
                int m = 1 << (NQH-1-q);
                for (int i = 0; i < 16; i++)
                    if (!(i & m)) {
                        float a0 = psi[i], a1 = psi[i|m];
                        psi[i] = c*a0 - s*a1; psi[i|m] = s*a0 + c*a1;
                    }
            }
            for (int q = 0; q < NQH; q++) {
                int cm = 1 << (NQH-1-q), tm = 1 << (NQH-1-((q+1)%NQH));
                for (int i = 0; i < 16; i++)
                    if ((i & cm) && !(i & tm)) {
                        float tmp = psi[i]; psi[i] = psi[i|tm]; psi[i|tm] = tmp;
                    }
            }
        }
        for (int q = 0; q < NQH; q++) {
            int m = 1 << (NQH-1-q);
            float z = 0.f, xe = 0.f;
            for (int i = 0; i < 16; i++) {
                z  += ((i & m) ? -1.f : 1.f) * psi[i]*psi[i];
                xe += psi[i]*psi[i^m];
            }
            g_attA[t*NQH+q] = z; g_attB[t*NQH+q] = -xe;
        }
    }
    if (t == HH) {
        for (int i = 0; i < 256; i++) fpsi[i] = 0.f;
        fpsi[0] = 1.f;
        for (int q = 0; q < NQF; q++) {
            float th = 0.5f * fp[q];
            float c = cosf(th), s = sinf(th);
            int m = 1 << (NQF-1-q);
            for (int i = 0; i < 256; i++)
                if (!(i & m)) {
                    float a0 = fpsi[i], a1 = fpsi[i|m];
                    fpsi[i] = c*a0 - s*a1; fpsi[i|m] = s*a0 + c*a1;
                }
        }
        for (int q = 0; q < NQF; q++) {
            int cm = 1 << (NQF-1-q), tm = 1 << (NQF-1-((q+1)%NQF));
            for (int i = 0; i < 256; i++)
                if ((i & cm) && !(i & tm)) {
                    float tmp = fpsi[i]; fpsi[i] = fpsi[i|tm]; fpsi[i|tm] = tmp;
                }
        }
        for (int q = 0; q < NQF; q++) {
            int m = 1 << (NQF-1-q);
            float z = 0.f, xe = 0.f;
            for (int i = 0; i < 256; i++) {
                z  += ((i & m) ? -1.f : 1.f) * fpsi[i]*fpsi[i];
                xe += fpsi[i]*fpsi[i^m];
            }
            g_ffnA[q] = z; g_ffnB[q] = -xe;
        }
    }
}

// ---- elementwise tf32 rounding (float4) ------------------------------------
__global__ void k_round4(const float* __restrict__ in, float* __restrict__ out)
{
    const int i = blockIdx.x*256 + threadIdx.x;
    float4 v = ((const float4*)in)[i];
    v.x = f2tf(v.x); v.y = f2tf(v.y); v.z = f2tf(v.z); v.w = f2tf(v.w);
    ((float4*)out)[i] = v;
}

// ---- build packed+rounded [wq; wk; wv_compact; 0] weight ------------------
__global__ void k_prep_wqkv(const float* __restrict__ wq, const float* __restrict__ wk,
                            const float* __restrict__ wv, float* __restrict__ w)
{
    const int idx = blockIdx.x*256 + threadIdx.x;      // NQKV*EE
    const int n = idx >> 9, k = idx & 511;
    float v;
    if      (n < 512)  v = wq[(size_t)n*EE + k];
    else if (n < 1024) v = wk[(size_t)(n-512)*EE + k];
    else if (n < 1056) { int j = n - 1024; v = wv[(size_t)((j>>2)*HD + (j&3))*EE + k]; }
    else               v = 0.f;
    w[idx] = f2tf(v);
}

// ---- compact V transpose: vTc[b][j][t] = qkv[b*TT+t][1024+j] ---------------
__global__ void k_vtransc()
{
    __shared__ float tile[32][33];
    const int b = blockIdx.z, t0 = blockIdx.x*32;
    const int tx = threadIdx.x, ty = threadIdx.y;          // (32, 8)
    #pragma unroll
    for (int i = 0; i < 32; i += 8)
        tile[ty+i][tx] = d_qkv[(size_t)(b*TT + t0+ty+i)*NQKV + 1024 + tx];
    __syncthreads();
    #pragma unroll
    for (int i = 0; i < 32; i += 8)
        d_vTc[(size_t)b*32*TT + (size_t)(ty+i)*TT + t0+tx] = tile[tx][ty+i];
}

// ---- 2-read softmax over rows of 2048, tf32-rounded output -----------------
__global__ void __launch_bounds__(256) k_softmax(float* __restrict__ S)
{
    const size_t row = blockIdx.x;
    float4* p = (float4*)(S + row*(size_t)TT);
    const int t = threadIdx.x;
    __shared__ float red[256];
    float4 x0 = p[t], x1 = p[t + 256];
    float m = fmaxf(fmaxf(fmaxf(x0.x,x0.y), fmaxf(x0.z,x0.w)),
                    fmaxf(fmaxf(x1.x,x1.y), fmaxf(x1.z,x1.w)));
    red[t] = m; __syncthreads();
    for (int st = 128; st > 0; st >>= 1) { if (t < st) red[t] = fmaxf(red[t], red[t+st]); __syncthreads(); }
    m = red[0]; __syncthreads();
    float4 e0, e1;
    e0.x = __expf(x0.x - m); e0.y = __expf(x0.y - m); e0.z = __expf(x0.z - m); e0.w = __expf(x0.w - m);
    e1.x = __expf(x1.x - m); e1.y = __expf(x1.y - m); e1.z = __expf(x1.z - m); e1.w = __expf(x1.w - m);
    red[t] = e0.x+e0.y+e0.z+e0.w + e1.x+e1.y+e1.z+e1.w; __syncthreads();
    for (int st = 128; st > 0; st >>= 1) { if (t < st) red[t] += red[t+st]; __syncthreads(); }
    const float inv = 1.f / red[0];
    e0.x = f2tf(e0.x*inv); e0.y = f2tf(e0.y*inv); e0.z = f2tf(e0.z*inv); e0.w = f2tf(e0.w*inv);
    e1.x = f2tf(e1.x*inv); e1.y = f2tf(e1.y*inv); e1.z = f2tf(e1.z*inv); e1.w = f2tf(e1.w*inv);
    p[t] = e0; p[t + 256] = e1;
}

// ---- quantum head map on compact o: q32[bt][j] = A_j cos(u)+B_j sin(u) -----
__global__ void k_qmap(float* __restrict__ q32)
{
    const int idx = blockIdx.x*256 + threadIdx.x;      // BTN*32
    const int j = idx & 31;
    const float u = d_o[idx];
    q32[idx] = f2tf(g_attA[j]*cosf(u) + g_attB[j]*sinf(u));
}

// ---- compact wo: woc[e][j] = wo[e][(j>>2)*64 + (j&3)] ----------------------
__global__ void k_woc(const float* __restrict__ wo, float* __restrict__ woc)
{
    const int idx = blockIdx.x*256 + threadIdx.x;      // EE*32
    const int e = idx >> 5, j = idx & 31;
    woc[idx] = f2tf(wo[(size_t)e*EE + (j>>2)*HD + (j&3)]);
}

// ---- pad w1 [2048,8] -> [2048,32], rounded ---------------------------------
__global__ void k_w1pad(const float* __restrict__ w1, float* __restrict__ w1p)
{
    const int idx = blockIdx.x*256 + threadIdx.x;      // FFND*32
    const int f = idx >> 5, j = idx & 31;
    w1p[idx] = (j < 8) ? f2tf(w1[f*8 + j]) : 0.f;
}

// ---- FFN quantum map (padded to K=32), rounded -----------------------------
__global__ void k_f8(float* __restrict__ f8p)
{
    const int idx = blockIdx.x*256 + threadIdx.x;      // BTN*32
    const int bt = idx >> 5, j = idx & 31;
    float r = 0.f;
    if (j < 8) {
        const float u = d_x1[(size_t)bt*EE + j];
        r = f2tf(g_ffnA[j]*cosf(u) + g_ffnB[j]*sinf(u));
    }
    f8p[idx] = r;
}

// ---- generic residual LayerNorm: out = LN(a + c) ---------------------------
__global__ void __launch_bounds__(256) k_ln(
    const float* __restrict__ a, const float* __restrict__ c,
    const float* __restrict__ g, const float* __restrict__ bb, float* __restrict__ out)
{
    const size_t bt = blockIdx.x;
    __shared__ float red[256];
    const int t = threadIdx.x;
    float v0 = a[bt*EE + t]       + c[bt*EE + t];
    float v1 = a[bt*EE + t + 256] + c[bt*EE + t + 256];
    red[t] = v0 + v1; __syncthreads();
    for (int st = 128; st > 0; st >>= 1) { if (t < st) red[t] += red[t+st]; __syncthreads(); }
    const float mean = red[0] * (1.f/EE);
    __syncthreads();
    float d0 = v0 - mean, d1 = v1 - mean;
    red[t] = d0*d0 + d1*d1; __syncthreads();
    for (int st = 128; st > 0; st >>= 1) { if (t < st) red[t] += red[t+st]; __syncthreads(); }
    const float rstd = rsqrtf(red[0]*(1.f/EE) + 1e-5f);
    out[bt*EE + t]       = d0*rstd*g[t]     + bb[t];
    out[bt*EE + t + 256] = d1*rstd*g[t+256] + bb[t+256];
}

// ============================================================================
extern "C" void kernel_launch(void* const* d_in, const int* in_sizes, int n_in,
                              void* d_out, int out_size)
{
    const float* x  = (const float*)d_in[0];
    const float* wq = (const float*)d_in[1];
    const float* wk = (const float*)d_in[2];
    const float* wv = (const float*)d_in[3];
    const float* wo = (const float*)d_in[4];
    const float* hp = (const float*)d_in[5];
    const float* fp = (const float*)d_in[6];
    const float* w1 = (const float*)d_in[7];
    const float* w2 = (const float*)d_in[8];
    const float* g1 = (const float*)d_in[9];
    const float* b1 = (const float*)d_in[10];
    const float* g2 = (const float*)d_in[11];
    const float* b2 = (const float*)d_in[12];
    float* out = (float*)d_out;

    const int SM128 = NSTAGE*(128+128)*32*4;   // 98304
    const int SM32  = NSTAGE*(128+32)*32*4;    // 61440
    cudaFuncSetAttribute(gemm_mma<128>, cudaFuncAttributeMaxDynamicSharedMemorySize, SM128);
    cudaFuncSetAttribute(gemm_mma<32>,  cudaFuncAttributeMaxDynamicSharedMemorySize, SM32);

    float *pxr, *pwqkv, *pqkv, *pvTc, *ps, *po, *pq32, *pwoc, *patt, *px1, *pf8, *pw1p, *pw2r, *ph1, *pf;
    cudaGetSymbolAddress((void**)&pxr,   d_xr);
    cudaGetSymbolAddress((void**)&pwqkv, d_wqkv);
    cudaGetSymbolAddress((void**)&pqkv,  d_qkv);
    cudaGetSymbolAddress((void**)&pvTc,  d_vTc);
    cudaGetSymbolAddress((void**)&ps,    d_s);
    cudaGetSymbolAddress((void**)&po,    d_o);
    cudaGetSymbolAddress((void**)&pq32,  d_q32);
    cudaGetSymbolAddress((void**)&pwoc,  d_woc);
    cudaGetSymbolAddress((void**)&patt,  d_att);
    cudaGetSymbolAddress((void**)&px1,   d_x1);
    cudaGetSymbolAddress((void**)&pf8,   d_f8);
    cudaGetSymbolAddress((void**)&pw1p,  d_w1p);
    cudaGetSymbolAddress((void**)&pw2r,  d_w2r);
    cudaGetSymbolAddress((void**)&ph1,   d_h1);
    cudaGetSymbolAddress((void**)&pf,    d_f);

    // ---- prep: circuit constants + tf32-rounded operands ----
    k_circuits<<<1, 32>>>(hp, fp);
    k_round4<<<(BTN*EE/4)/256, 256>>>(x,  pxr);
    k_round4<<<(EE*FFND/4)/256, 256>>>(w2, pw2r);
    k_prep_wqkv<<<(NQKV*EE)/256, 256>>>(wq, wk, wv, pwqkv);
    k_woc<<<(EE*32)/256, 256>>>(wo, pwoc);
    k_w1pad<<<(FFND*32)/256, 256>>>(w1, pw1p);

    // ---- fused QKV projection (q | k | v_compact), rounded output ----
    gemm_mma<128><<<dim3(NQKV/128, BTN/128, 1), 256, SM128>>>(
        pxr, pwqkv, pqkv, BTN, NQKV, EE, EE, EE, NQKV, 1.f, 0, 1, 0, 0, 0);

    // ---- compact V transpose ----
    k_vtransc<<<dim3(TT/32, 1, BB), dim3(32, 8)>>>();

    // ---- scores = q k^T / sqrt(E) ----
    gemm_mma<128><<<dim3(TT/128, TT/128, BB), 256, SM128>>>(
        pqkv, pqkv + 512, ps, TT, TT, EE, NQKV, NQKV, TT, 0.044194173824159216f, 0, 0,
        (size_t)TT*NQKV, (size_t)TT*NQKV, (size_t)TT*TT);

    k_softmax<<<BTN, 256>>>(ps);

    // ---- o = attn @ v_compact (N = 32 only!) ----
    gemm_mma<32><<<dim3(1, TT/128, BB), 256, SM32>>>(
        ps, pvTc, po, TT, 32, TT, TT, TT, 32, 1.f, 0, 0,
        (size_t)TT*TT, (size_t)32*TT, (size_t)TT*32);

    // ---- quantum head map + wo projection + LN1 ----
    k_qmap<<<(BTN*32)/256, 256>>>(pq32);
    gemm_mma<128><<<dim3(EE/128, BTN/128, 1), 256, SM128>>>(
        pq32, pwoc, patt, BTN, EE, 32, 32, 32, EE, 1.f, 0, 0, 0, 0, 0);
    k_ln<<<BTN, 256>>>(x, patt, g1, b1, px1);

    // ---- FFN: quantum map -> w1(+relu) -> w2 ----
    k_f8<<<(BTN*32)/256, 256>>>(pf8);
    gemm_mma<128><<<dim3(FFND/128, BTN/128, 1), 256, SM128>>>(
        pf8, pw1p, ph1, BTN, FFND, 32, 32, 32, FFND, 1.f, 1, 1, 0, 0, 0);
    gemm_mma<128><<<dim3(EE/128, BTN/128, 1), 256, SM128>>>(
        ph1, pw2r, pf, BTN, EE, FFND, FFND, FFND, EE, 1.f, 0, 0, 0, 0, 0);

    k_ln<<<BTN, 256>>>(px1, pf, g2, b2, out);
}